// round 12
// baseline (speedup 1.0000x reference)
#include <cuda_runtime.h>
#include <math.h>

// Problem constants
#define BB 2048
#define TT 200
#define DD 64
#define H1 80
#define H2 40
#define NTHR 288

#define KTRS 202   // k_tr i-row stride: even (8B align); 202%32=10 -> 2-way max conflicts
#define WES  772   // weff slot stride: %4==0, 772%32=4 -> banks 4*JS distinct
#define WIS  12    // weff i-stride within slot (10 data + 2 pad)
#define H1TS 204   // h1T row stride
#define W2RS 96    // w2p row stride: slots of 12, banks 12*js mod 32 distinct
#define LSTR 204   // g_logits row stride (padded)

// Shared memory layout kernel 1 (float offsets)
#define OFF_KTR   0        // 64*202 = 12928
#define OFF_WEFF  12928    // 8*772 = 6176 -> 19104
#define OFF_H1T   0        // 80*204 = 16320 (< 19104), aliases ktr+weff; dead after layer 1
#define OFF_W2P   19104    // 80*96 = 7680 -> 26784 (row-permuted, slot-padded W2)
#define OFF_Q     26784    // 64
#define OFF_CP    26848    // 8*80 = 640
#define OFF_WF    27488    // 40
#define OFF_B2    27528    // 40
#define OFF_BF    27568    // 8
#define SMEM_FLOATS 27576
#define SMEM_BYTES  (SMEM_FLOATS * 4)    // 110304 B/CTA, x2 = 220.6KB <= 227KB

typedef unsigned long long ull;

__device__ float g_logits[BB * LSTR];   // static scratch (allocation-free)

// ---- packed f32x2 helpers (sm_100+; ptxas never auto-fuses) ----
__device__ __forceinline__ ull pack2(float lo, float hi) {
    ull r;
    asm("mov.b64 %0, {%1, %2};" : "=l"(r) : "r"(__float_as_uint(lo)), "r"(__float_as_uint(hi)));
    return r;
}
__device__ __forceinline__ void unpack2(ull v, float& lo, float& hi) {
    unsigned int a, b;
    asm("mov.b64 {%0, %1}, %2;" : "=r"(a), "=r"(b) : "l"(v));
    lo = __uint_as_float(a);
    hi = __uint_as_float(b);
}
__device__ __forceinline__ void fma2(ull& d, ull a, ull b) {
    asm("fma.rn.f32x2 %0, %1, %2, %0;" : "+l"(d) : "l"(a), "l"(b));
}

// ======================= Kernel 1: per-(b,t) MLP logits =======================
__global__ void __launch_bounds__(NTHR, 2)
din_logits_kernel(const float* __restrict__ q,
                  const float* __restrict__ k,
                  const float* __restrict__ W1,
                  const float* __restrict__ b1,
                  const float* __restrict__ a1,
                  const float* __restrict__ W2,
                  const float* __restrict__ b2,
                  const float* __restrict__ a2,
                  const float* __restrict__ Wf,
                  const float* __restrict__ bf)
{
    extern __shared__ float sm[];

    const int tid  = threadIdx.x;
    const int b    = blockIdx.x;
    const int lane = tid & 31;

    const int TG  = tid >> 3;                        // t-group 0..35 (6 t each)
    const int JS  = tid & 7;                         // j-slot 0..7 (10 j1 each)
    const int NTG = 34;                              // ceil(200/6)
    const int TGC = (TG < NTG) ? TG : (NTG - 1);
    const int t0  = 6 * TGC;

    // ---------------- Phase A: stage data ----------------
    if (tid < DD) sm[OFF_Q + tid] = q[(size_t)b * DD + tid];
    {
        // k -> k_tr[i][t] transpose via float4 LDG
        const float4* kb4 = reinterpret_cast<const float4*>(k + (size_t)b * TT * DD);
        #pragma unroll 4
        for (int x = tid; x < TT * DD / 4; x += NTHR) {
            float4 vv = kb4[x];
            int t = x >> 4;            // 16 float4 per row
            int i = (x & 15) * 4;
            float* dst = sm + OFF_KTR + t;
            dst[(i + 0) * KTRS] = vv.x;
            dst[(i + 1) * KTRS] = vv.y;
            dst[(i + 2) * KTRS] = vv.z;
            dst[(i + 3) * KTRS] = vv.w;
        }
    }
    {
        // W2 -> row/slot-permuted w2p: physical row pj holds logical j1 = 10*(pj%8) + pj/8,
        // columns in slots of 12 (5 data + 7 pad? no: slot js holds j2 = 5*js..5*js+4 at js*12..js*12+4)
        for (int x = tid; x < H1 * H2; x += NTHR) {
            int pj = x / H2, j2 = x - pj * H2;
            int j1 = 10 * (pj & 7) + (pj >> 3);
            int slot = j2 / 5, cc = j2 - slot * 5;
            sm[OFF_W2P + pj * W2RS + slot * 12 + cc] = W2[j1 * H2 + j2];
        }
    }
    if (tid < H2) sm[OFF_WF + tid] = Wf[tid];
    if (tid >= 64 && tid < 64 + H2) sm[OFF_B2 + tid - 64] = b2[tid - 64];
    if (tid == 104) sm[OFF_BF] = bf[0];
    __syncthreads();   // q (and k_tr/w2p) ready

    // ---------------- Phase B: weff (float4) + c partials (float4) ----------------
    // weff[slot js][i][jj] for j1 = 10*js + jj; task = float4 over j
    #pragma unroll 3
    for (int x = tid; x < DD * H1 / 4; x += NTHR) {
        int i  = x / 20;
        int j  = (x - i * 20) * 4;
        const float4 wb4 = *reinterpret_cast<const float4*>(W1 + (DD + i) * H1 + j);
        const float4 wc4 = *reinterpret_cast<const float4*>(W1 + (2 * DD + i) * H1 + j);
        const float4 wd4 = *reinterpret_cast<const float4*>(W1 + (3 * DD + i) * H1 + j);
        float qv = sm[OFF_Q + i];
        float wv[4] = {wb4.x - wc4.x + qv * wd4.x,
                       wb4.y - wc4.y + qv * wd4.y,
                       wb4.z - wc4.z + qv * wd4.z,
                       wb4.w - wc4.w + qv * wd4.w};
        #pragma unroll
        for (int e = 0; e < 4; e++) {
            int jj = j + e;
            int slot = jj / 10, jr = jj - slot * 10;
            sm[OFF_WEFF + slot * WES + i * WIS + jr] = wv[e];
        }
    }
    // c partials: 8 chunks x 20 threads, float4 over j; b1 folded into chunk 0
    if (tid < 160) {
        int ch = tid / 20;          // 0..7
        int jq = tid - ch * 20;     // float4 column
        int j  = 4 * jq;
        float4 c4 = (ch == 0) ? *reinterpret_cast<const float4*>(b1 + j)
                              : make_float4(0.f, 0.f, 0.f, 0.f);
        #pragma unroll
        for (int i = ch * 8; i < ch * 8 + 8; i++) {
            float qv = sm[OFF_Q + i];
            float4 wa = *reinterpret_cast<const float4*>(W1 + i * H1 + j);
            float4 wc = *reinterpret_cast<const float4*>(W1 + (2 * DD + i) * H1 + j);
            c4.x += qv * (wa.x + wc.x);
            c4.y += qv * (wa.y + wc.y);
            c4.z += qv * (wa.z + wc.z);
            c4.w += qv * (wa.w + wc.w);
        }
        *reinterpret_cast<float4*>(sm + OFF_CP + ch * 80 + j) = c4;
    }
    __syncthreads();

    // ---------------- Layer 1: 6t x 10j tile, h packed over t-pairs ----------------
    ull h[30];   // h[tp*10 + j], tp = t-pair 0..2, j1 = 10*JS + j
    {
        const float* cp = sm + OFF_CP + 10 * JS;
        #pragma unroll
        for (int j = 0; j < 10; j++) {
            float cv = cp[j];
            #pragma unroll
            for (int ch = 1; ch < 8; ch++) cv += cp[ch * 80 + j];
            ull cc = pack2(cv, cv);
            h[j] = cc; h[10 + j] = cc; h[20 + j] = cc;
        }
    }
    {
        const float* kro = sm + OFF_KTR + t0;
        const float* wro = sm + OFF_WEFF + JS * WES;
        #pragma unroll 2
        for (int i = 0; i < DD; i++) {
            const ull* kp = reinterpret_cast<const ull*>(kro + i * KTRS);
            ull k01 = kp[0], k23 = kp[1], k45 = kp[2];
            const float* wrow = wro + i * WIS;
            float4 w0 = *reinterpret_cast<const float4*>(wrow);
            float4 w1 = *reinterpret_cast<const float4*>(wrow + 4);
            float2 w2v = *reinterpret_cast<const float2*>(wrow + 8);
            float wsc[10] = {w0.x, w0.y, w0.z, w0.w, w1.x, w1.y, w1.z, w1.w, w2v.x, w2v.y};
            #pragma unroll
            for (int j = 0; j < 10; j++) {
                ull wd = pack2(wsc[j], wsc[j]);
                fma2(h[j],      k01, wd);
                fma2(h[10 + j], k23, wd);
                fma2(h[20 + j], k45, wd);
            }
        }
    }
    __syncthreads();   // ktr + weff dead; safe to overwrite with h1T

    // ---------------- PReLU 1 + permuted transpose store: row pj = j*8 + JS ----------------
    {
        #pragma unroll
        for (int tp = 0; tp < 3; tp++) {
            int ta = t0 + 2 * tp;
            const float2* pL = reinterpret_cast<const float2*>(a1 + ta * H1 + 10 * JS);
            const float2* pH = reinterpret_cast<const float2*>(a1 + (ta + 1) * H1 + 10 * JS);
            float2 aL[5], aH[5];
            #pragma unroll
            for (int p = 0; p < 5; p++) { aL[p] = __ldg(pL + p); aH[p] = __ldg(pH + p); }
            float al[10] = {aL[0].x, aL[0].y, aL[1].x, aL[1].y, aL[2].x, aL[2].y, aL[3].x, aL[3].y, aL[4].x, aL[4].y};
            float ah[10] = {aH[0].x, aH[0].y, aH[1].x, aH[1].y, aH[2].x, aH[2].y, aH[3].x, aH[3].y, aH[4].x, aH[4].y};
            #pragma unroll
            for (int j = 0; j < 10; j++) {
                float x0, x1; unpack2(h[tp * 10 + j], x0, x1);
                x0 = (x0 > 0.f) ? x0 : al[j] * x0;
                x1 = (x1 > 0.f) ? x1 : ah[j] * x1;
                int pj = j * 8 + JS;
                *reinterpret_cast<float2*>(sm + OFF_H1T + pj * H1TS + ta) = make_float2(x0, x1);
            }
        }
    }
    __syncthreads();

    // ---------------- a2 / wf prefetch (h[] dead -> register room) ----------------
    float a2r[6][5], wfr[5];
    {
        #pragma unroll
        for (int tp = 0; tp < 3; tp++) {
            const float* base = a2 + (t0 + 2 * tp) * H2 + 5 * JS;
            #pragma unroll
            for (int c = 0; c < 5; c++) {
                a2r[2 * tp][c]     = __ldg(base + c);
                a2r[2 * tp + 1][c] = __ldg(base + H2 + c);
            }
        }
        #pragma unroll
        for (int c = 0; c < 5; c++) wfr[c] = sm[OFF_WF + 5 * JS + c];
    }

    // ---------------- Layer 2: 6t x 5j2 tile over permuted rows ----------------
    {
        ull g[15];   // g[tp*5 + c]
        const float* b2p = sm + OFF_B2 + 5 * JS;
        #pragma unroll
        for (int c = 0; c < 5; c++) {
            float bv = b2p[c];
            ull bb2 = pack2(bv, bv);
            g[c] = bb2; g[5 + c] = bb2; g[10 + c] = bb2;
        }
        const float* hb  = sm + OFF_H1T + t0;
        const float* w2b = sm + OFF_W2P + 12 * JS;
        #pragma unroll 4
        for (int pj = 0; pj < H1; pj++) {
            const ull* hp = reinterpret_cast<const ull*>(hb + pj * H1TS);
            ull hA = hp[0], hB = hp[1], hC = hp[2];
            const float* wp = w2b + pj * W2RS;
            float4 w4 = *reinterpret_cast<const float4*>(wp);
            float  w5 = wp[4];
            float wv[5] = {w4.x, w4.y, w4.z, w4.w, w5};
            #pragma unroll
            for (int c = 0; c < 5; c++) {
                ull ww = pack2(wv[c], wv[c]);
                fma2(g[c],      hA, ww);
                fma2(g[5 + c],  hB, ww);
                fma2(g[10 + c], hC, ww);
            }
        }

        // PReLU 2 + final dot -> per-(t, JS) partial logits
        float lg[6];
        #pragma unroll
        for (int tp = 0; tp < 3; tp++) {
            float la = 0.f, lb = 0.f;
            #pragma unroll
            for (int c = 0; c < 5; c++) {
                float x0, x1; unpack2(g[tp * 5 + c], x0, x1);
                float p0 = a2r[2 * tp][c], p1 = a2r[2 * tp + 1][c];
                x0 = (x0 > 0.f) ? x0 : p0 * x0;
                x1 = (x1 > 0.f) ? x1 : p1 * x1;
                la += x0 * wfr[c]; lb += x1 * wfr[c];
            }
            lg[2 * tp] = la; lg[2 * tp + 1] = lb;
        }
        // reduce over the 8 JS lanes (quarter-warp; quarters are TG-homogeneous)
        const unsigned qmask = 0xFFu << ((lane >> 3) << 3);
        #pragma unroll
        for (int o = 1; o < 8; o <<= 1) {
            #pragma unroll
            for (int r = 0; r < 6; r++)
                lg[r] += __shfl_xor_sync(qmask, lg[r], o);
        }
        if (JS == 0 && TG < NTG) {
            float bfv = sm[OFF_BF];
            float* lp = g_logits + (size_t)b * LSTR + t0;
            *reinterpret_cast<float2*>(lp)     = make_float2(lg[0] + bfv, lg[1] + bfv);
            *reinterpret_cast<float2*>(lp + 2) = make_float2(lg[2] + bfv, lg[3] + bfv);
            *reinterpret_cast<float2*>(lp + 4) = make_float2(lg[4] + bfv, lg[5] + bfv);
        }
    }
}

// ======================= Kernel 2: softmax + weighted V sum =======================
__global__ void __launch_bounds__(256)
din_softmax_v_kernel(const float* __restrict__ v, float* __restrict__ out)
{
    __shared__ float lbuf[TT];
    __shared__ float rbuf[32];
    __shared__ float vpart[512];

    const int tid  = threadIdx.x;
    const int b    = blockIdx.x;
    const int lane = tid & 31;
    const int warp = tid >> 5;

    const bool valid = (tid < TT);
    float logit = valid ? g_logits[(size_t)b * LSTR + tid] : -3.4e38f;

    float x = logit;
    #pragma unroll
    for (int o = 16; o; o >>= 1) x = fmaxf(x, __shfl_xor_sync(0xffffffffu, x, o));
    if (lane == 0) rbuf[warp] = x;
    __syncthreads();
    if (warp == 0) {
        float y = (lane < 8) ? rbuf[lane] : -3.4e38f;
        #pragma unroll
        for (int o = 4; o; o >>= 1) y = fmaxf(y, __shfl_xor_sync(0xffffffffu, y, o));
        if (lane == 0) rbuf[0] = y;
    }
    __syncthreads();
    const float m = rbuf[0];

    float e = valid ? __expf(logit - m) : 0.f;
    float s = e;
    #pragma unroll
    for (int o = 16; o; o >>= 1) s += __shfl_xor_sync(0xffffffffu, s, o);
    if (lane == 0) rbuf[16 + warp] = s;
    __syncthreads();
    if (warp == 0) {
        float y = (lane < 8) ? rbuf[16 + lane] : 0.f;
        #pragma unroll
        for (int o = 4; o; o >>= 1) y += __shfl_xor_sync(0xffffffffu, y, o);
        if (lane == 0) rbuf[16] = y;
    }
    __syncthreads();
    const float inv = 1.f / rbuf[16];
    if (valid) lbuf[tid] = e * inv;
    __syncthreads();

    // out[b][d] = sum_t w[t] * v[b][t][d]  (float2 loads, coalesced, high MLP)
    {
        const int d2  = tid & 31;    // float2 column 0..31
        const int grp = tid >> 5;    // 0..7
        const float2* vb = reinterpret_cast<const float2*>(v + (size_t)b * TT * DD) + d2;
        float ax = 0.f, ay = 0.f;
        #pragma unroll 5
        for (int t2 = grp; t2 < TT; t2 += 8) {
            float w = lbuf[t2];
            float2 vv = __ldg(vb + t2 * 32);
            ax += w * vv.x; ay += w * vv.y;
        }
        *reinterpret_cast<float2*>(vpart + grp * 64 + 2 * d2) = make_float2(ax, ay);
    }
    __syncthreads();
    if (tid < DD) {
        float r = 0.f;
        #pragma unroll
        for (int g2 = 0; g2 < 8; g2++) r += vpart[g2 * 64 + tid];
        out[(size_t)b * DD + tid] = r;
    }
}

extern "C" void kernel_launch(void* const* d_in, const int* in_sizes, int n_in,
                              void* d_out, int out_size)
{
    const float* q  = (const float*)d_in[0];
    const float* k  = (const float*)d_in[1];
    const float* v  = (const float*)d_in[2];
    const float* W1 = (const float*)d_in[3];
    const float* b1 = (const float*)d_in[4];
    const float* a1 = (const float*)d_in[5];
    const float* W2 = (const float*)d_in[6];
    const float* b2 = (const float*)d_in[7];
    const float* a2 = (const float*)d_in[8];
    const float* Wf = (const float*)d_in[9];
    const float* bf = (const float*)d_in[10];
    float* out = (float*)d_out;

    cudaFuncSetAttribute(din_logits_kernel,
                         cudaFuncAttributeMaxDynamicSharedMemorySize, SMEM_BYTES);
    din_logits_kernel<<<BB, NTHR, SMEM_BYTES>>>(q, k, W1, b1, a1, W2, b2, a2, Wf, bf);
    din_softmax_v_kernel<<<BB, 256>>>(v, out);
}

// round 15
// speedup vs baseline: 1.0808x; 1.0808x over previous
#include <cuda_runtime.h>
#include <math.h>

// Problem constants
#define BB 2048
#define TT 200
#define DD 64
#define H1 80
#define H2 40
#define NTHR 288

#define KTRS 202   // k_tr i-row stride: even (8B align); 202%32=10 -> 2-way max conflicts
#define WES  772   // weff slot stride: %4==0, 772%32=4 -> banks 4*JS distinct
#define WIS  12    // weff i-stride within slot (10 data + 2 pad)
#define H1R  84    // h1 natural row stride (floats): 336B, %16==0; t-phases {0,8,16,24} conflict-free
#define W2R  84    // W2T row stride (same properties)
#define LSTR 204   // g_logits row stride (padded)

// Shared memory layout kernel 1 (float offsets)
#define OFF_KTR   0        // 64*202 = 12928
#define OFF_WEFF  12928    // 8*772 = 6176 -> 19104
#define OFF_H1N   0        // 200*84 = 16800 (< 19104), aliases ktr+weff; used strictly after layer 1
#define OFF_W2T   19104    // 40*84 = 3360 -> 22464 (transposed W2: [j2][j1])
#define OFF_Q     22464    // 64
#define OFF_CP    22528    // 8*80 = 640
#define OFF_WF    23168    // 40
#define OFF_B2    23208    // 40
#define OFF_BF    23248    // 8
#define SMEM_FLOATS 23256
#define SMEM_BYTES  (SMEM_FLOATS * 4)    // 93KB/CTA, x2 = 186KB <= 227KB

typedef unsigned long long ull;

__device__ float g_logits[BB * LSTR];   // static scratch (allocation-free)

// ---- packed f32x2 helpers (sm_100+; ptxas never auto-fuses) ----
__device__ __forceinline__ ull pack2(float lo, float hi) {
    ull r;
    asm("mov.b64 %0, {%1, %2};" : "=l"(r) : "r"(__float_as_uint(lo)), "r"(__float_as_uint(hi)));
    return r;
}
__device__ __forceinline__ void unpack2(ull v, float& lo, float& hi) {
    unsigned int a, b;
    asm("mov.b64 {%0, %1}, %2;" : "=r"(a), "=r"(b) : "l"(v));
    lo = __uint_as_float(a);
    hi = __uint_as_float(b);
}
__device__ __forceinline__ void fma2(ull& d, ull a, ull b) {
    asm("fma.rn.f32x2 %0, %1, %2, %0;" : "+l"(d) : "l"(a), "l"(b));
}

// ======================= Kernel 1: per-(b,t) MLP logits =======================
__global__ void __launch_bounds__(NTHR, 2)
din_logits_kernel(const float* __restrict__ q,
                  const float* __restrict__ k,
                  const float* __restrict__ W1,
                  const float* __restrict__ b1,
                  const float* __restrict__ a1,
                  const float* __restrict__ W2,
                  const float* __restrict__ b2,
                  const float* __restrict__ a2,
                  const float* __restrict__ Wf,
                  const float* __restrict__ bf)
{
    extern __shared__ float sm[];

    const int tid  = threadIdx.x;
    const int b    = blockIdx.x;
    const int lane = tid & 31;

    const int TG  = tid >> 3;                        // t-group 0..35 (6 t each)
    const int JS  = tid & 7;                         // j-slot 0..7 (10 j1 each)
    const int NTG = 34;                              // ceil(200/6)
    const int TGC = (TG < NTG) ? TG : (NTG - 1);
    const int t0  = 6 * TGC;

    // ---------------- Phase A: stage data ----------------
    if (tid < DD) sm[OFF_Q + tid] = q[(size_t)b * DD + tid];
    {
        // k -> k_tr[i][t] transpose via float4 LDG
        const float4* kb4 = reinterpret_cast<const float4*>(k + (size_t)b * TT * DD);
        #pragma unroll 4
        for (int x = tid; x < TT * DD / 4; x += NTHR) {
            float4 vv = kb4[x];
            int t = x >> 4;            // 16 float4 per row
            int i = (x & 15) * 4;
            float* dst = sm + OFF_KTR + t;
            dst[(i + 0) * KTRS] = vv.x;
            dst[(i + 1) * KTRS] = vv.y;
            dst[(i + 2) * KTRS] = vv.z;
            dst[(i + 3) * KTRS] = vv.w;
        }
    }
    {
        // W2 -> transposed W2T[j2][j1] (coalesced LDG, scattered STS - one time)
        for (int x = tid; x < H1 * H2; x += NTHR) {
            int j1 = x / H2, j2 = x - j1 * H2;
            sm[OFF_W2T + j2 * W2R + j1] = W2[x];
        }
    }
    if (tid < H2) sm[OFF_WF + tid] = Wf[tid];
    if (tid >= 64 && tid < 64 + H2) sm[OFF_B2 + tid - 64] = b2[tid - 64];
    if (tid == 104) sm[OFF_BF] = bf[0];
    __syncthreads();   // q (and k_tr/w2t) ready

    // ---------------- Phase B: weff (float4) + c partials (float4) ----------------
    #pragma unroll 3
    for (int x = tid; x < DD * H1 / 4; x += NTHR) {
        int i  = x / 20;
        int j  = (x - i * 20) * 4;
        const float4 wb4 = *reinterpret_cast<const float4*>(W1 + (DD + i) * H1 + j);
        const float4 wc4 = *reinterpret_cast<const float4*>(W1 + (2 * DD + i) * H1 + j);
        const float4 wd4 = *reinterpret_cast<const float4*>(W1 + (3 * DD + i) * H1 + j);
        float qv = sm[OFF_Q + i];
        float wv[4] = {wb4.x - wc4.x + qv * wd4.x,
                       wb4.y - wc4.y + qv * wd4.y,
                       wb4.z - wc4.z + qv * wd4.z,
                       wb4.w - wc4.w + qv * wd4.w};
        #pragma unroll
        for (int e = 0; e < 4; e++) {
            int jj = j + e;
            int slot = jj / 10, jr = jj - slot * 10;
            sm[OFF_WEFF + slot * WES + i * WIS + jr] = wv[e];
        }
    }
    // c partials: 8 chunks x 20 threads, float4 over j; b1 folded into chunk 0
    if (tid < 160) {
        int ch = tid / 20;          // 0..7
        int jq = tid - ch * 20;     // float4 column
        int j  = 4 * jq;
        float4 c4 = (ch == 0) ? *reinterpret_cast<const float4*>(b1 + j)
                              : make_float4(0.f, 0.f, 0.f, 0.f);
        #pragma unroll
        for (int i = ch * 8; i < ch * 8 + 8; i++) {
            float qv = sm[OFF_Q + i];
            float4 wa = *reinterpret_cast<const float4*>(W1 + i * H1 + j);
            float4 wc = *reinterpret_cast<const float4*>(W1 + (2 * DD + i) * H1 + j);
            c4.x += qv * (wa.x + wc.x);
            c4.y += qv * (wa.y + wc.y);
            c4.z += qv * (wa.z + wc.z);
            c4.w += qv * (wa.w + wc.w);
        }
        *reinterpret_cast<float4*>(sm + OFF_CP + ch * 80 + j) = c4;
    }
    __syncthreads();

    // ---------------- Layer 1: 6t x 10j tile, h packed over t-pairs ----------------
    ull h[30];   // h[tp*10 + j], tp = t-pair 0..2, j1 = 10*JS + j
    {
        const float* cp = sm + OFF_CP + 10 * JS;
        #pragma unroll
        for (int j = 0; j < 10; j++) {
            float cv = cp[j];
            #pragma unroll
            for (int ch = 1; ch < 8; ch++) cv += cp[ch * 80 + j];
            ull cc = pack2(cv, cv);
            h[j] = cc; h[10 + j] = cc; h[20 + j] = cc;
        }
    }
    {
        const float* kro = sm + OFF_KTR + t0;
        const float* wro = sm + OFF_WEFF + JS * WES;
        #pragma unroll 2
        for (int i = 0; i < DD; i++) {
            const ull* kp = reinterpret_cast<const ull*>(kro + i * KTRS);
            ull k01 = kp[0], k23 = kp[1], k45 = kp[2];
            const float* wrow = wro + i * WIS;
            float4 w0 = *reinterpret_cast<const float4*>(wrow);
            float4 w1 = *reinterpret_cast<const float4*>(wrow + 4);
            float2 w2v = *reinterpret_cast<const float2*>(wrow + 8);
            float wsc[10] = {w0.x, w0.y, w0.z, w0.w, w1.x, w1.y, w1.z, w1.w, w2v.x, w2v.y};
            #pragma unroll
            for (int j = 0; j < 10; j++) {
                ull wd = pack2(wsc[j], wsc[j]);
                fma2(h[j],      k01, wd);
                fma2(h[10 + j], k23, wd);
                fma2(h[20 + j], k45, wd);
            }
        }
    }
    __syncthreads();   // ktr + weff dead; safe to overwrite with h1 (natural layout)

    // ---------------- PReLU 1 + NATURAL store: h1[t][j1], j1 = 10*JS + j ----------------
    {
        #pragma unroll
        for (int tp = 0; tp < 3; tp++) {
            int ta = t0 + 2 * tp;
            const float2* pL = reinterpret_cast<const float2*>(a1 + ta * H1 + 10 * JS);
            const float2* pH = reinterpret_cast<const float2*>(a1 + (ta + 1) * H1 + 10 * JS);
            float2 aL[5], aH[5];
            #pragma unroll
            for (int p = 0; p < 5; p++) { aL[p] = __ldg(pL + p); aH[p] = __ldg(pH + p); }
            float al[10] = {aL[0].x, aL[0].y, aL[1].x, aL[1].y, aL[2].x, aL[2].y, aL[3].x, aL[3].y, aL[4].x, aL[4].y};
            float ah[10] = {aH[0].x, aH[0].y, aH[1].x, aH[1].y, aH[2].x, aH[2].y, aH[3].x, aH[3].y, aH[4].x, aH[4].y};
            float* r0 = sm + OFF_H1N + ta * H1R + 10 * JS;
            float* r1 = r0 + H1R;
            #pragma unroll
            for (int j = 0; j < 10; j++) {
                float x0, x1; unpack2(h[tp * 10 + j], x0, x1);
                x0 = (x0 > 0.f) ? x0 : al[j] * x0;
                x1 = (x1 > 0.f) ? x1 : ah[j] * x1;
                r0[j] = x0;
                r1[j] = x1;
            }
        }
    }
    __syncthreads();

    // ---------------- Layer 2: K-parity packed, 6t x 5j2 tile ----------------
    // g[t*5+c] = f32x2 (even-pj partial, odd-pj partial); finalize lo+hi.
    {
        ull g[30];
        const float* b2p = sm + OFF_B2 + 5 * JS;
        #pragma unroll
        for (int c = 0; c < 5; c++) {
            ull bb2 = pack2(b2p[c], 0.f);
            #pragma unroll
            for (int t = 0; t < 6; t++) g[t * 5 + c] = bb2;
        }
        const float* hb = sm + OFF_H1N + t0 * H1R;
        const float* wb = sm + OFF_W2T + (5 * JS) * W2R;
        #pragma unroll 2
        for (int pq = 0; pq < H1 / 4; pq++) {
            ulonglong2 hq[6];
            #pragma unroll
            for (int t = 0; t < 6; t++)
                hq[t] = *reinterpret_cast<const ulonglong2*>(hb + t * H1R + pq * 4);
            #pragma unroll
            for (int c = 0; c < 5; c++) {
                ulonglong2 wq = *reinterpret_cast<const ulonglong2*>(wb + c * W2R + pq * 4);
                #pragma unroll
                for (int t = 0; t < 6; t++) {
                    fma2(g[t * 5 + c], hq[t].x, wq.x);
                    fma2(g[t * 5 + c], hq[t].y, wq.y);
                }
            }
        }

        // PReLU 2 + final dot -> per-(t, JS) partial logits
        float wfr[5];
        #pragma unroll
        for (int c = 0; c < 5; c++) wfr[c] = sm[OFF_WF + 5 * JS + c];
        // batched a2 loads (after GEMM: h/w regs dead)
        float a2r[6][5];
        #pragma unroll
        for (int t = 0; t < 6; t++) {
            const float* base = a2 + (t0 + t) * H2 + 5 * JS;
            #pragma unroll
            for (int c = 0; c < 5; c++) a2r[t][c] = __ldg(base + c);
        }
        float lg[6];
        #pragma unroll
        for (int t = 0; t < 6; t++) {
            float la = 0.f;
            #pragma unroll
            for (int c = 0; c < 5; c++) {
                float lo, hi; unpack2(g[t * 5 + c], lo, hi);
                float gv = lo + hi;
                float av = a2r[t][c];
                gv = (gv > 0.f) ? gv : av * gv;
                la += gv * wfr[c];
            }
            lg[t] = la;
        }
        // reduce over the 8 JS lanes (quarter-warp; quarters are TG-homogeneous)
        const unsigned qmask = 0xFFu << ((lane >> 3) << 3);
        #pragma unroll
        for (int o = 1; o < 8; o <<= 1) {
            #pragma unroll
            for (int r = 0; r < 6; r++)
                lg[r] += __shfl_xor_sync(qmask, lg[r], o);
        }
        if (JS == 0 && TG < NTG) {
            float bfv = sm[OFF_BF];
            float* lp = g_logits + (size_t)b * LSTR + t0;
            *reinterpret_cast<float2*>(lp)     = make_float2(lg[0] + bfv, lg[1] + bfv);
            *reinterpret_cast<float2*>(lp + 2) = make_float2(lg[2] + bfv, lg[3] + bfv);
            *reinterpret_cast<float2*>(lp + 4) = make_float2(lg[4] + bfv, lg[5] + bfv);
        }
    }
}

// ======================= Kernel 2: softmax + weighted V sum (at HBM roof) =======================
__global__ void __launch_bounds__(256)
din_softmax_v_kernel(const float* __restrict__ v, float* __restrict__ out)
{
    __shared__ float lbuf[TT];
    __shared__ float rbuf[32];
    __shared__ float vpart[512];

    const int tid  = threadIdx.x;
    const int b    = blockIdx.x;
    const int lane = tid & 31;
    const int warp = tid >> 5;

    const bool valid = (tid < TT);
    float logit = valid ? g_logits[(size_t)b * LSTR + tid] : -3.4e38f;

    float x = logit;
    #pragma unroll
    for (int o = 16; o; o >>= 1) x = fmaxf(x, __shfl_xor_sync(0xffffffffu, x, o));
    if (lane == 0) rbuf[warp] = x;
    __syncthreads();
    if (warp == 0) {
        float y = (lane < 8) ? rbuf[lane] : -3.4e38f;
        #pragma unroll
        for (int o = 4; o; o >>= 1) y = fmaxf(y, __shfl_xor_sync(0xffffffffu, y, o));
        if (lane == 0) rbuf[0] = y;
    }
    __syncthreads();
    const float m = rbuf[0];

    float e = valid ? __expf(logit - m) : 0.f;
    float s = e;
    #pragma unroll
    for (int o = 16; o; o >>= 1) s += __shfl_xor_sync(0xffffffffu, s, o);
    if (lane == 0) rbuf[16 + warp] = s;
    __syncthreads();
    if (warp == 0) {
        float y = (lane < 8) ? rbuf[16 + lane] : 0.f;
        #pragma unroll
        for (int o = 4; o; o >>= 1) y += __shfl_xor_sync(0xffffffffu, y, o);
        if (lane == 0) rbuf[16] = y;
    }
    __syncthreads();
    const float inv = 1.f / rbuf[16];
    if (valid) lbuf[tid] = e * inv;
    __syncthreads();

    // out[b][d] = sum_t w[t] * v[b][t][d]  (float2 loads, coalesced, high MLP)
    {
        const int d2  = tid & 31;    // float2 column 0..31
        const int grp = tid >> 5;    // 0..7
        const float2* vb = reinterpret_cast<const float2*>(v + (size_t)b * TT * DD) + d2;
        float ax = 0.f, ay = 0.f;
        #pragma unroll 5
        for (int t2 = grp; t2 < TT; t2 += 8) {
            float w = lbuf[t2];
            float2 vv = __ldg(vb + t2 * 32);
            ax += w * vv.x; ay += w * vv.y;
        }
        *reinterpret_cast<float2*>(vpart + grp * 64 + 2 * d2) = make_float2(ax, ay);
    }
    __syncthreads();
    if (tid < DD) {
        float r = 0.f;
        #pragma unroll
        for (int g2 = 0; g2 < 8; g2++) r += vpart[g2 * 64 + tid];
        out[(size_t)b * DD + tid] = r;
    }
}

extern "C" void kernel_launch(void* const* d_in, const int* in_sizes, int n_in,
                              void* d_out, int out_size)
{
    const float* q  = (const float*)d_in[0];
    const float* k  = (const float*)d_in[1];
    const float* v  = (const float*)d_in[2];
    const float* W1 = (const float*)d_in[3];
    const float* b1 = (const float*)d_in[4];
    const float* a1 = (const float*)d_in[5];
    const float* W2 = (const float*)d_in[6];
    const float* b2 = (const float*)d_in[7];
    const float* a2 = (const float*)d_in[8];
    const float* Wf = (const float*)d_in[9];
    const float* bf = (const float*)d_in[10];
    float* out = (float*)d_out;

    cudaFuncSetAttribute(din_logits_kernel,
                         cudaFuncAttributeMaxDynamicSharedMemorySize, SMEM_BYTES);
    din_logits_kernel<<<BB, NTHR, SMEM_BYTES>>>(q, k, W1, b1, a1, W2, b2, a2, Wf, bf);
    din_softmax_v_kernel<<<BB, 256>>>(v, out);
}